// round 12
// baseline (speedup 1.0000x reference)
#include <cuda_runtime.h>

#define NN 50000
#define EE 800000
#define DH 128
#define DE 16
#define LLAY 3
#define NBLK 49   // ceil(NN/1024)

typedef unsigned long long u64;

// ---------- packed f32x2 helpers (sm_103a FFMA2) ----------
__device__ __forceinline__ u64 pk2(float x, float y) {
    u64 r;
    asm("mov.b64 %0, {%1, %2};" : "=l"(r) : "r"(__float_as_uint(x)), "r"(__float_as_uint(y)));
    return r;
}
__device__ __forceinline__ float2 up2(u64 v) {
    unsigned lo, hi;
    asm("mov.b64 {%0, %1}, %2;" : "=r"(lo), "=r"(hi) : "l"(v));
    return make_float2(__uint_as_float(lo), __uint_as_float(hi));
}
__device__ __forceinline__ u64 ffma2(u64 a, u64 b, u64 c) {
    u64 d;
    asm("fma.rn.f32x2 %0, %1, %2, %3;" : "=l"(d) : "l"(a), "l"(b), "l"(c));
    return d;
}

// ---------- device scratch ----------
__device__ int   g_deg[NN];            // zero at load; re-zeroed by last msgln
__device__ int   g_rowptr[NN + 1];
__device__ int   g_cursor[NN];
__device__ float g_dis[NN];
__device__ volatile int g_incl[NBLK];  // decoupled-lookback inclusive prefixes
__device__ volatile int g_flag[NBLK];  // zero at load; re-zeroed by last msgln
__device__ int   g_rowS[EE];
__device__ float g_eaS[(size_t)EE * DE];
__device__ float g_S[(size_t)NN * DH * LLAY];
__device__ float g_hx[(size_t)NN * DH];
__device__ float g_Q[(size_t)NN * DH * LLAY];
__device__ float g_h[(size_t)NN * DH];

// ---------- launch 0: histogram ----------
__global__ void k_hist(const int* __restrict__ col) {
    int e = blockIdx.x * blockDim.x + threadIdx.x;
    if (e < EE) atomicAdd(&g_deg[col[e]], 1);
}

// ---------- launch 1: decoupled-lookback scan (part+off+add fused) ----------
__global__ void k_scanpf() {
    __shared__ int sh[32];
    __shared__ int sPrev;
    int b = blockIdx.x, tid = threadIdx.x;
    int i = b * 1024 + tid;
    int v = (i < NN) ? g_deg[i] : 0;
    int lane = tid & 31, wid = tid >> 5;
    int x = v;
    #pragma unroll
    for (int off = 1; off < 32; off <<= 1) {
        int t = __shfl_up_sync(0xffffffffu, x, off);
        if (lane >= off) x += t;
    }
    if (lane == 31) sh[wid] = x;
    __syncthreads();
    if (wid == 0) {
        int y = sh[lane];
        #pragma unroll
        for (int off = 1; off < 32; off <<= 1) {
            int t = __shfl_up_sync(0xffffffffu, y, off);
            if (lane >= off) y += t;
        }
        sh[lane] = y;
    }
    __syncthreads();
    int total = sh[31];
    if (tid == 0) {
        int prev = 0;
        if (b > 0) {
            while (g_flag[b - 1] == 0) { __nanosleep(32); }
            __threadfence();
            prev = g_incl[b - 1];
        }
        g_incl[b] = prev + total;
        __threadfence();
        g_flag[b] = 1;
        sPrev = prev;
        if (b == 0) g_rowptr[NN] = EE;
    }
    __syncthreads();
    int excl = x - v + ((wid > 0) ? sh[wid - 1] : 0) + sPrev;
    if (i < NN) {
        g_rowptr[i] = excl;
        g_cursor[i] = excl;
        g_dis[i] = (v > 0) ? rsqrtf((float)v) : 0.0f;
    }
}

// ---------- launch 2: scatter edges into CSR(dst) order ----------
__global__ void k_scatter(const int* __restrict__ row, const int* __restrict__ col,
                          const float* __restrict__ ea) {
    int e = blockIdx.x * blockDim.x + threadIdx.x;
    if (e >= EE) return;
    int c = col[e];
    int pos = atomicAdd(&g_cursor[c], 1);
    g_rowS[pos] = row[e];
    const float4* s = (const float4*)(ea + (size_t)e * DE);
    float4* d = (float4*)(g_eaS + (size_t)pos * DE);
    d[0] = s[0]; d[1] = s[1]; d[2] = s[2]; d[3] = s[3];
}

// ---------- launch 3: edge-MLP hidden + segment sum ----------
// 2 warps per (node, layer): lane covers 2 cols -> weights = 16 u64 regs,
// targeting 3 blocks/SM (37.5% occ) vs 112-reg/21% before
__global__ __launch_bounds__(256, 3) void k_spass(const float* __restrict__ ew1,
                                                  const float* __restrict__ eb1) {
    __shared__ __align__(16) float sEdge[8][32 * DE];   // 2KB per warp
    int wIn  = threadIdx.x >> 5;
    int gw   = (blockIdx.x << 3) + wIn;       // warp id over NN*LLAY*2
    int lane = threadIdx.x & 31;
    int v    = gw / (LLAY * 2);
    int rem  = gw - v * (LLAY * 2);
    int l    = rem >> 1;
    int d0   = (rem & 1) * 64 + lane * 2;

    // W1 slice k-pair packed: wpj[kp] = (W1[2kp][d0+j], W1[2kp+1][d0+j])
    u64 wp0[8], wp1[8];
    const float* W1 = ew1 + (size_t)l * DE * DH;
    #pragma unroll
    for (int kp = 0; kp < 8; kp++) {
        float2 r0 = *(const float2*)(W1 + (2 * kp)     * DH + d0);
        float2 r1 = *(const float2*)(W1 + (2 * kp + 1) * DH + d0);
        wp0[kp] = pk2(r0.x, r1.x);
        wp1[kp] = pk2(r0.y, r1.y);
    }
    float2 b1 = *(const float2*)(eb1 + l * DH + d0);
    u64 bi0 = pk2(b1.x, 0.f), bi1 = pk2(b1.y, 0.f);

    float a0 = 0.f, a1 = 0.f;
    int e0 = g_rowptr[v], e1 = g_rowptr[v + 1];
    float* buf = sEdge[wIn];
    for (int base = e0; base < e1; base += 32) {
        int n = min(32, e1 - base);
        __syncwarp();
        const float4* src = (const float4*)(g_eaS + (size_t)base * DE);
        #pragma unroll
        for (int c = 0; c < 4; c++) {
            int idx = c * 32 + lane;
            if (idx < n * 4) ((float4*)buf)[idx] = src[idx];
        }
        __syncwarp();
        for (int i = 0; i < n; i++) {
            const u64* ep = (const u64*)(buf + i * DE);  // broadcast LDS.64
            u64 t0 = bi0, t1 = bi1;
            #pragma unroll
            for (int kp = 0; kp < 8; kp++) {
                u64 e = ep[kp];
                t0 = ffma2(e, wp0[kp], t0);
                t1 = ffma2(e, wp1[kp], t1);
            }
            float2 f0 = up2(t0), f1 = up2(t1);
            a0 += fmaxf(f0.x + f0.y, 0.0f);
            a1 += fmaxf(f1.x + f1.y, 0.0f);
        }
    }
    *(float2*)(g_S + (size_t)v * (DH * LLAY) + l * DH + d0) = make_float2(a0, a1);
}

// ---------- dense GEMM body: C[M,128] = A[M,*] @ B[128,128], optional row scaling ----------
__device__ __forceinline__ void gemm_body(const float* __restrict__ A, int lda,
                                          const float* __restrict__ B,
                                          float* __restrict__ C, int M,
                                          float* sm, int bx,
                                          const float* __restrict__ rscale) {
    float* As = sm;                      // 64 x 128 f32
    u64* Bsp  = (u64*)(sm + 64 * 128);   // [64 kk][128 c] k-paired
    int tid = threadIdx.x;               // 256
    int m0  = bx * 64;

    #pragma unroll
    for (int i = 0; i < 8; i++) {
        int lin = (i * 256 + tid) * 4;
        int r = lin >> 7, k = lin & 127;
        float4 vv = make_float4(0.f, 0.f, 0.f, 0.f);
        if (m0 + r < M) vv = *(const float4*)(A + (size_t)(m0 + r) * lda + k);
        *(float4*)(As + lin) = vv;
    }
    #pragma unroll
    for (int i = 0; i < 32; i++) {
        int idx = i * 256 + tid;
        int kk = idx >> 7, c = idx & 127;
        Bsp[idx] = pk2(B[(2 * kk) * 128 + c], B[(2 * kk + 1) * 128 + c]);
    }
    __syncthreads();

    int cbase = (tid & 31) * 4;
    int rbase = (tid >> 5) * 8;
    u64 acc[8][4];
    #pragma unroll
    for (int i = 0; i < 8; i++) {
        acc[i][0] = 0ull; acc[i][1] = 0ull; acc[i][2] = 0ull; acc[i][3] = 0ull;
    }
    const u64* Asd = (const u64*)As;
    #pragma unroll 8
    for (int kk = 0; kk < 64; kk++) {
        const ulonglong2* bp = (const ulonglong2*)(Bsp + kk * 128 + cbase);
        ulonglong2 b01 = bp[0];
        ulonglong2 b23 = bp[1];
        #pragma unroll
        for (int i = 0; i < 8; i++) {
            u64 a = Asd[(size_t)(rbase + i) * 64 + kk];
            acc[i][0] = ffma2(a, b01.x, acc[i][0]);
            acc[i][1] = ffma2(a, b01.y, acc[i][1]);
            acc[i][2] = ffma2(a, b23.x, acc[i][2]);
            acc[i][3] = ffma2(a, b23.y, acc[i][3]);
        }
    }
    #pragma unroll
    for (int i = 0; i < 8; i++) {
        int r = m0 + rbase + i;
        if (r < M) {
            float2 t0 = up2(acc[i][0]), t1 = up2(acc[i][1]);
            float2 t2 = up2(acc[i][2]), t3 = up2(acc[i][3]);
            float sc = rscale ? rscale[r] : 1.0f;
            float4 o = make_float4((t0.x + t0.y) * sc, (t1.x + t1.y) * sc,
                                   (t2.x + t2.y) * sc, (t3.x + t3.y) * sc);
            *(float4*)(C + (size_t)r * 128 + cbase) = o;
        }
    }
}

// batched: y==0 -> hx0 = dis*(x@linW0) ; y==1..3 -> Q_l = S_l@W2_l
__global__ __launch_bounds__(256) void k_gemm4(const float* __restrict__ x,
                                               const float* __restrict__ linw,
                                               const float* __restrict__ ew2) {
    extern __shared__ float sm[];
    const float* A; int lda; const float* B; float* C; const float* rs;
    if (blockIdx.y == 0) {
        A = x; lda = 128; B = linw; C = g_hx; rs = g_dis;
    } else {
        int l = blockIdx.y - 1;
        A = g_S + l * DH; lda = DH * LLAY;
        B = ew2 + (size_t)l * DH * DH;
        C = g_Q + (size_t)l * NN * DH; rs = 0;
    }
    gemm_body(A, lda, B, C, NN, sm, blockIdx.x, rs);
}

__global__ __launch_bounds__(256) void k_gemm(const float* __restrict__ A, int lda,
                                              const float* __restrict__ B,
                                              float* __restrict__ C, int M) {
    extern __shared__ float sm[];
    gemm_body(A, lda, B, C, M, sm, blockIdx.x, g_dis);  // hx GEMMs dis-scaled
}

// ---------- gather + aggregate + LayerNorm + ReLU (one warp per node) ----------
__global__ void k_msgln(const float* __restrict__ hx, const float* __restrict__ Q,
                        const float* __restrict__ b2, const float* __restrict__ bi,
                        const float* __restrict__ lw, const float* __restrict__ lb,
                        float* __restrict__ out, int clearDeg) {
    int gt = blockIdx.x * blockDim.x + threadIdx.x;
    int v = gt >> 5, lane = gt & 31;
    if (v >= NN) return;
    int d0 = lane * 4;
    float a0 = 0.f, a1 = 0.f, a2 = 0.f, a3 = 0.f;
    int e0 = g_rowptr[v], e1 = g_rowptr[v + 1];
    for (int base = e0; base < e1; base += 32) {
        int idx = base + lane;
        int rr = (idx < e1) ? g_rowS[idx] : 0;
        int n = min(32, e1 - base);
        #pragma unroll 4
        for (int j = 0; j < n; j++) {
            int r = __shfl_sync(0xffffffffu, rr, j);
            float4 hv = *(const float4*)(hx + (size_t)r * 128 + d0);
            a0 += hv.x; a1 += hv.y; a2 += hv.z; a3 += hv.w;
        }
    }
    float degf = (float)g_deg[v];
    float disv = g_dis[v];
    if (clearDeg) {                       // reset persistent state for next replay
        if (lane == 0) g_deg[v] = 0;
        if (lane == 1 && v < NBLK) g_flag[v] = 0;
    }
    float4 q  = *(const float4*)(Q + (size_t)v * 128 + d0);
    float4 c2 = *(const float4*)(b2 + d0);
    float4 cb = *(const float4*)(bi + d0);
    float x0 = a0 * disv + q.x + degf * c2.x + cb.x;
    float x1 = a1 * disv + q.y + degf * c2.y + cb.y;
    float x2 = a2 * disv + q.z + degf * c2.z + cb.z;
    float x3 = a3 * disv + q.w + degf * c2.w + cb.w;
    float s = x0 + x1 + x2 + x3;
    #pragma unroll
    for (int off = 16; off; off >>= 1) s += __shfl_xor_sync(0xffffffffu, s, off);
    float mu = s * (1.0f / 128.0f);
    float e0f = x0 - mu, e1f = x1 - mu, e2f = x2 - mu, e3f = x3 - mu;
    float vs = e0f * e0f + e1f * e1f + e2f * e2f + e3f * e3f;
    #pragma unroll
    for (int off = 16; off; off >>= 1) vs += __shfl_xor_sync(0xffffffffu, vs, off);
    float inv = rsqrtf(vs * (1.0f / 128.0f) + 1e-5f);
    float4 w4 = *(const float4*)(lw + d0);
    float4 b4 = *(const float4*)(lb + d0);
    float4 o;
    o.x = fmaxf(e0f * inv * w4.x + b4.x, 0.f);
    o.y = fmaxf(e1f * inv * w4.y + b4.y, 0.f);
    o.z = fmaxf(e2f * inv * w4.z + b4.z, 0.f);
    o.w = fmaxf(e3f * inv * w4.w + b4.w, 0.f);
    *(float4*)(out + (size_t)v * 128 + d0) = o;
}

extern "C" void kernel_launch(void* const* d_in, const int* in_sizes, int n_in,
                              void* d_out, int out_size) {
    const float* x    = (const float*)d_in[0];
    const float* ea   = (const float*)d_in[1];
    const float* linw = (const float*)d_in[2];
    const float* ew1  = (const float*)d_in[3];
    const float* eb1  = (const float*)d_in[4];
    const float* ew2  = (const float*)d_in[5];
    const float* eb2  = (const float*)d_in[6];
    const float* bias = (const float*)d_in[7];
    const float* lnw  = (const float*)d_in[8];
    const float* lnb  = (const float*)d_in[9];
    const int*   eidx = (const int*)d_in[10];
    const int* rowp = eidx;
    const int* colp = eidx + EE;
    float* out = (float*)d_out;

    cudaFuncSetAttribute(k_gemm,  cudaFuncAttributeMaxDynamicSharedMemorySize, 98304);
    cudaFuncSetAttribute(k_gemm4, cudaFuncAttributeMaxDynamicSharedMemorySize, 98304);

    float *hx, *Q, *h;
    cudaGetSymbolAddress((void**)&hx, g_hx);
    cudaGetSymbolAddress((void**)&Q,  g_Q);
    cudaGetSymbolAddress((void**)&h,  g_h);

    // CSR build: hist(0), decoupled-lookback scan(1), scatter(2)
    k_hist<<<(EE + 255) / 256, 256>>>(colp);
    k_scanpf<<<NBLK, 1024>>>();
    k_scatter<<<(EE + 255) / 256, 256>>>(rowp, colp, ea);

    // launch index 3: k_spass (ncu -s/-c window)
    k_spass<<<NN * LLAY * 2 / 8, 256>>>(ew1, eb1);

    // batched: hx0 + Q0..Q2 in one launch
    {
        dim3 grid((NN + 63) / 64, 4);
        k_gemm4<<<grid, 256, 98304>>>(x, linw, ew2);
    }

    for (int l = 0; l < LLAY; l++) {
        if (l > 0)
            k_gemm<<<(NN + 63) / 64, 256, 98304>>>(h, 128, linw + (size_t)l * 128 * 128, hx, NN);
        float* ho = (l == LLAY - 1) ? out : h;
        k_msgln<<<(NN * 32 + 255) / 256, 256>>>(hx, Q + (size_t)l * NN * DH,
                                                eb2 + l * 128, bias + l * 128,
                                                lnw + l * 128, lnb + l * 128, ho,
                                                l == LLAY - 1 ? 1 : 0);
    }
}

// round 16
// speedup vs baseline: 1.1047x; 1.1047x over previous
#include <cuda_runtime.h>

#define NN 50000
#define EE 800000
#define DH 128
#define DE 16
#define LLAY 3
#define NBLK 49   // ceil(NN/1024)

typedef unsigned long long u64;

// ---------- packed f32x2 helpers (sm_103a FFMA2) ----------
__device__ __forceinline__ u64 pk2(float x, float y) {
    u64 r;
    asm("mov.b64 %0, {%1, %2};" : "=l"(r) : "r"(__float_as_uint(x)), "r"(__float_as_uint(y)));
    return r;
}
__device__ __forceinline__ float2 up2(u64 v) {
    unsigned lo, hi;
    asm("mov.b64 {%0, %1}, %2;" : "=r"(lo), "=r"(hi) : "l"(v));
    return make_float2(__uint_as_float(lo), __uint_as_float(hi));
}
__device__ __forceinline__ u64 ffma2(u64 a, u64 b, u64 c) {
    u64 d;
    asm("fma.rn.f32x2 %0, %1, %2, %3;" : "=l"(d) : "l"(a), "l"(b), "l"(c));
    return d;
}

// ---------- device scratch ----------
__device__ int   g_deg[NN];          // zero at load; re-zeroed by last msgln
__device__ int   g_rowptr[NN + 1];
__device__ int   g_cursor[NN];
__device__ float g_dis[NN];
__device__ int   g_bsum[64];
__device__ int   g_boff[64];
__device__ int   g_rowS[EE];
__device__ float g_eaS[(size_t)EE * DE];
__device__ float g_S[(size_t)NN * DH * LLAY];
__device__ float g_hx[(size_t)NN * DH];
__device__ float g_Q[(size_t)NN * DH * LLAY];
__device__ float g_h[(size_t)NN * DH];

// ---------- CSR build (3-phase scan, proven in the 687.8us run) ----------
__global__ void k_hist(const int* __restrict__ col) {
    int e = blockIdx.x * blockDim.x + threadIdx.x;
    if (e < EE) atomicAdd(&g_deg[col[e]], 1);
}

__global__ void k_part() {
    __shared__ int sh[32];
    int b = blockIdx.x, tid = threadIdx.x;
    int i = b * 1024 + tid;
    int v = (i < NN) ? g_deg[i] : 0;
    if (i < NN) g_dis[i] = (v > 0) ? rsqrtf((float)v) : 0.0f;
    int lane = tid & 31, wid = tid >> 5;
    int x = v;
    #pragma unroll
    for (int off = 1; off < 32; off <<= 1) {
        int t = __shfl_up_sync(0xffffffffu, x, off);
        if (lane >= off) x += t;
    }
    if (lane == 31) sh[wid] = x;
    __syncthreads();
    if (wid == 0) {
        int y = sh[lane];
        #pragma unroll
        for (int off = 1; off < 32; off <<= 1) {
            int t = __shfl_up_sync(0xffffffffu, y, off);
            if (lane >= off) y += t;
        }
        sh[lane] = y;
    }
    __syncthreads();
    int excl = x - v + ((wid > 0) ? sh[wid - 1] : 0);
    if (i < NN) g_rowptr[i] = excl;
    if (tid == 1023) g_bsum[b] = sh[31];
}

__global__ void k_off() {
    __shared__ int s[64];
    int t = threadIdx.x;
    int v = (t < NBLK) ? g_bsum[t] : 0;
    s[t] = v;
    __syncthreads();
    #pragma unroll
    for (int off = 1; off < 64; off <<= 1) {
        int tv = (t >= off) ? s[t - off] : 0;
        __syncthreads();
        s[t] += tv;
        __syncthreads();
    }
    g_boff[t] = s[t] - v;  // exclusive
}

__global__ void k_add() {
    int b = blockIdx.x, tid = threadIdx.x;
    int i = b * 1024 + tid;
    if (i < NN) {
        int r = g_rowptr[i] + g_boff[b];
        g_rowptr[i] = r;
        g_cursor[i] = r;
    }
    if (b == 0 && tid == 0) g_rowptr[NN] = EE;
}

__global__ void k_scatter(const int* __restrict__ row, const int* __restrict__ col,
                          const float* __restrict__ ea) {
    int e = blockIdx.x * blockDim.x + threadIdx.x;
    if (e >= EE) return;
    int c = col[e];
    int pos = atomicAdd(&g_cursor[c], 1);
    g_rowS[pos] = row[e];
    const float4* s = (const float4*)(ea + (size_t)e * DE);
    float4* d = (float4*)(g_eaS + (size_t)pos * DE);
    d[0] = s[0]; d[1] = s[1]; d[2] = s[2]; d[3] = s[3];
}

// ---------- edge-MLP hidden + segment sum, cooperative 3-warp blocks ----------
// one block (96 thr) per node; warp w = layer w; edge tile staged ONCE for
// all 3 layers; per-warp v1 layout (4 cols/lane, 64 weight regs), LDS.128 reads
__global__ __launch_bounds__(96, 6) void k_spass(const float* __restrict__ ew1,
                                                 const float* __restrict__ eb1) {
    __shared__ __align__(16) float buf[32 * DE];   // 2KB: one 32-edge tile
    int tid  = threadIdx.x;
    int l    = tid >> 5;                 // warp in block = layer
    int lane = tid & 31;
    int v    = blockIdx.x;
    int d0   = lane * 4;

    // W1 slice k-pair packed: wp[j][kp] = (W1[2kp][d0+j], W1[2kp+1][d0+j])
    u64 wp[4][8];
    const float* W1 = ew1 + (size_t)l * DE * DH;
    #pragma unroll
    for (int kp = 0; kp < 8; kp++) {
        float4 r0 = *(const float4*)(W1 + (2 * kp)     * DH + d0);
        float4 r1 = *(const float4*)(W1 + (2 * kp + 1) * DH + d0);
        wp[0][kp] = pk2(r0.x, r1.x);
        wp[1][kp] = pk2(r0.y, r1.y);
        wp[2][kp] = pk2(r0.z, r1.z);
        wp[3][kp] = pk2(r0.w, r1.w);
    }
    float4 b1 = *(const float4*)(eb1 + l * DH + d0);
    u64 binit[4] = { pk2(b1.x, 0.f), pk2(b1.y, 0.f), pk2(b1.z, 0.f), pk2(b1.w, 0.f) };

    float acc[4] = {0.f, 0.f, 0.f, 0.f};
    int e0 = g_rowptr[v], e1 = g_rowptr[v + 1];
    for (int base = e0; base < e1; base += 32) {
        int n = min(32, e1 - base);
        __syncthreads();                          // WAR on buf
        const float4* src = (const float4*)(g_eaS + (size_t)base * DE);
        for (int idx = tid; idx < n * 4; idx += 96)
            ((float4*)buf)[idx] = src[idx];
        __syncthreads();
        for (int i = 0; i < n; i++) {
            const ulonglong2* ep2 = (const ulonglong2*)(buf + i * DE);  // broadcast LDS.128
            ulonglong2 q0 = ep2[0], q1 = ep2[1], q2 = ep2[2], q3 = ep2[3];
            #pragma unroll
            for (int j = 0; j < 4; j++) {
                u64 t = binit[j];
                t = ffma2(q0.x, wp[j][0], t);
                t = ffma2(q0.y, wp[j][1], t);
                t = ffma2(q1.x, wp[j][2], t);
                t = ffma2(q1.y, wp[j][3], t);
                t = ffma2(q2.x, wp[j][4], t);
                t = ffma2(q2.y, wp[j][5], t);
                t = ffma2(q3.x, wp[j][6], t);
                t = ffma2(q3.y, wp[j][7], t);
                float2 f = up2(t);
                acc[j] += fmaxf(f.x + f.y, 0.0f);
            }
        }
    }
    *(float4*)(g_S + (size_t)v * (DH * LLAY) + l * DH + d0) =
        make_float4(acc[0], acc[1], acc[2], acc[3]);
}

// ---------- dense GEMM body: C[M,128] = A[M,*] @ B[128,128], optional row scaling ----------
__device__ __forceinline__ void gemm_body(const float* __restrict__ A, int lda,
                                          const float* __restrict__ B,
                                          float* __restrict__ C, int M,
                                          float* sm, int bx,
                                          const float* __restrict__ rscale) {
    float* As = sm;                      // 64 x 128 f32
    u64* Bsp  = (u64*)(sm + 64 * 128);   // [64 kk][128 c] k-paired
    int tid = threadIdx.x;               // 256
    int m0  = bx * 64;

    #pragma unroll
    for (int i = 0; i < 8; i++) {
        int lin = (i * 256 + tid) * 4;
        int r = lin >> 7, k = lin & 127;
        float4 vv = make_float4(0.f, 0.f, 0.f, 0.f);
        if (m0 + r < M) vv = *(const float4*)(A + (size_t)(m0 + r) * lda + k);
        *(float4*)(As + lin) = vv;
    }
    #pragma unroll
    for (int i = 0; i < 32; i++) {
        int idx = i * 256 + tid;
        int kk = idx >> 7, c = idx & 127;
        Bsp[idx] = pk2(B[(2 * kk) * 128 + c], B[(2 * kk + 1) * 128 + c]);
    }
    __syncthreads();

    int cbase = (tid & 31) * 4;
    int rbase = (tid >> 5) * 8;
    u64 acc[8][4];
    #pragma unroll
    for (int i = 0; i < 8; i++) {
        acc[i][0] = 0ull; acc[i][1] = 0ull; acc[i][2] = 0ull; acc[i][3] = 0ull;
    }
    const u64* Asd = (const u64*)As;
    #pragma unroll 8
    for (int kk = 0; kk < 64; kk++) {
        const ulonglong2* bp = (const ulonglong2*)(Bsp + kk * 128 + cbase);
        ulonglong2 b01 = bp[0];
        ulonglong2 b23 = bp[1];
        #pragma unroll
        for (int i = 0; i < 8; i++) {
            u64 a = Asd[(size_t)(rbase + i) * 64 + kk];
            acc[i][0] = ffma2(a, b01.x, acc[i][0]);
            acc[i][1] = ffma2(a, b01.y, acc[i][1]);
            acc[i][2] = ffma2(a, b23.x, acc[i][2]);
            acc[i][3] = ffma2(a, b23.y, acc[i][3]);
        }
    }
    #pragma unroll
    for (int i = 0; i < 8; i++) {
        int r = m0 + rbase + i;
        if (r < M) {
            float2 t0 = up2(acc[i][0]), t1 = up2(acc[i][1]);
            float2 t2 = up2(acc[i][2]), t3 = up2(acc[i][3]);
            float sc = rscale ? rscale[r] : 1.0f;
            float4 o = make_float4((t0.x + t0.y) * sc, (t1.x + t1.y) * sc,
                                   (t2.x + t2.y) * sc, (t3.x + t3.y) * sc);
            *(float4*)(C + (size_t)r * 128 + cbase) = o;
        }
    }
}

// batched: y==0 -> hx0 = dis*(x@linW0) ; y==1..3 -> Q_l = S_l@W2_l
__global__ __launch_bounds__(256) void k_gemm4(const float* __restrict__ x,
                                               const float* __restrict__ linw,
                                               const float* __restrict__ ew2) {
    extern __shared__ float sm[];
    const float* A; int lda; const float* B; float* C; const float* rs;
    if (blockIdx.y == 0) {
        A = x; lda = 128; B = linw; C = g_hx; rs = g_dis;
    } else {
        int l = blockIdx.y - 1;
        A = g_S + l * DH; lda = DH * LLAY;
        B = ew2 + (size_t)l * DH * DH;
        C = g_Q + (size_t)l * NN * DH; rs = 0;
    }
    gemm_body(A, lda, B, C, NN, sm, blockIdx.x, rs);
}

__global__ __launch_bounds__(256) void k_gemm(const float* __restrict__ A, int lda,
                                              const float* __restrict__ B,
                                              float* __restrict__ C, int M) {
    extern __shared__ float sm[];
    gemm_body(A, lda, B, C, M, sm, blockIdx.x, g_dis);  // hx GEMMs dis-scaled
}

// ---------- gather + aggregate + LayerNorm + ReLU (one warp per node) ----------
__global__ void k_msgln(const float* __restrict__ hx, const float* __restrict__ Q,
                        const float* __restrict__ b2, const float* __restrict__ bi,
                        const float* __restrict__ lw, const float* __restrict__ lb,
                        float* __restrict__ out, int clearDeg) {
    int gt = blockIdx.x * blockDim.x + threadIdx.x;
    int v = gt >> 5, lane = gt & 31;
    if (v >= NN) return;
    int d0 = lane * 4;
    float a0 = 0.f, a1 = 0.f, a2 = 0.f, a3 = 0.f;
    int e0 = g_rowptr[v], e1 = g_rowptr[v + 1];
    for (int base = e0; base < e1; base += 32) {
        int idx = base + lane;
        int rr = (idx < e1) ? g_rowS[idx] : 0;
        int n = min(32, e1 - base);
        #pragma unroll 4
        for (int j = 0; j < n; j++) {
            int r = __shfl_sync(0xffffffffu, rr, j);
            float4 hv = *(const float4*)(hx + (size_t)r * 128 + d0);
            a0 += hv.x; a1 += hv.y; a2 += hv.z; a3 += hv.w;
        }
    }
    float degf = (float)g_deg[v];
    float disv = g_dis[v];
    if (clearDeg && lane == 0) g_deg[v] = 0;     // reset for next replay
    float4 q  = *(const float4*)(Q + (size_t)v * 128 + d0);
    float4 c2 = *(const float4*)(b2 + d0);
    float4 cb = *(const float4*)(bi + d0);
    float x0 = a0 * disv + q.x + degf * c2.x + cb.x;
    float x1 = a1 * disv + q.y + degf * c2.y + cb.y;
    float x2 = a2 * disv + q.z + degf * c2.z + cb.z;
    float x3 = a3 * disv + q.w + degf * c2.w + cb.w;
    float s = x0 + x1 + x2 + x3;
    #pragma unroll
    for (int off = 16; off; off >>= 1) s += __shfl_xor_sync(0xffffffffu, s, off);
    float mu = s * (1.0f / 128.0f);
    float e0f = x0 - mu, e1f = x1 - mu, e2f = x2 - mu, e3f = x3 - mu;
    float vs = e0f * e0f + e1f * e1f + e2f * e2f + e3f * e3f;
    #pragma unroll
    for (int off = 16; off; off >>= 1) vs += __shfl_xor_sync(0xffffffffu, vs, off);
    float inv = rsqrtf(vs * (1.0f / 128.0f) + 1e-5f);
    float4 w4 = *(const float4*)(lw + d0);
    float4 b4 = *(const float4*)(lb + d0);
    float4 o;
    o.x = fmaxf(e0f * inv * w4.x + b4.x, 0.f);
    o.y = fmaxf(e1f * inv * w4.y + b4.y, 0.f);
    o.z = fmaxf(e2f * inv * w4.z + b4.z, 0.f);
    o.w = fmaxf(e3f * inv * w4.w + b4.w, 0.f);
    *(float4*)(out + (size_t)v * 128 + d0) = o;
}

extern "C" void kernel_launch(void* const* d_in, const int* in_sizes, int n_in,
                              void* d_out, int out_size) {
    const float* x    = (const float*)d_in[0];
    const float* ea   = (const float*)d_in[1];
    const float* linw = (const float*)d_in[2];
    const float* ew1  = (const float*)d_in[3];
    const float* eb1  = (const float*)d_in[4];
    const float* ew2  = (const float*)d_in[5];
    const float* eb2  = (const float*)d_in[6];
    const float* bias = (const float*)d_in[7];
    const float* lnw  = (const float*)d_in[8];
    const float* lnb  = (const float*)d_in[9];
    const int*   eidx = (const int*)d_in[10];
    const int* rowp = eidx;
    const int* colp = eidx + EE;
    float* out = (float*)d_out;

    cudaFuncSetAttribute(k_gemm,  cudaFuncAttributeMaxDynamicSharedMemorySize, 98304);
    cudaFuncSetAttribute(k_gemm4, cudaFuncAttributeMaxDynamicSharedMemorySize, 98304);

    float *hx, *Q, *h;
    cudaGetSymbolAddress((void**)&hx, g_hx);
    cudaGetSymbolAddress((void**)&Q,  g_Q);
    cudaGetSymbolAddress((void**)&h,  g_h);

    // CSR build: hist, 3-phase scan, scatter  [g_deg starts zero, re-zeroed by last msgln]
    k_hist<<<(EE + 255) / 256, 256>>>(colp);
    k_part<<<NBLK, 1024>>>();
    k_off<<<1, 64>>>();
    k_add<<<NBLK, 1024>>>();
    k_scatter<<<(EE + 255) / 256, 256>>>(rowp, colp, ea);

    // edge-MLP hidden + segment-sum: one 96-thread block per node (3 layer-warps)
    k_spass<<<NN, 96>>>(ew1, eb1);

    // batched: hx0 + Q0..Q2 in one launch
    {
        dim3 grid((NN + 63) / 64, 4);
        k_gemm4<<<grid, 256, 98304>>>(x, linw, ew2);
    }

    for (int l = 0; l < LLAY; l++) {
        if (l > 0)
            k_gemm<<<(NN + 63) / 64, 256, 98304>>>(h, 128, linw + (size_t)l * 128 * 128, hx, NN);
        float* ho = (l == LLAY - 1) ? out : h;
        k_msgln<<<(NN * 32 + 255) / 256, 256>>>(hx, Q + (size_t)l * NN * DH,
                                                eb2 + l * 128, bias + l * 128,
                                                lnw + l * 128, lnb + l * 128, ho,
                                                l == LLAY - 1 ? 1 : 0);
    }
}